// round 5
// baseline (speedup 1.0000x reference)
#include <cuda_runtime.h>
#include <cuda_bf16.h>
#include <cstdint>

#define BATCH  32
#define LSEQ   1025
#define NTOK   513
#define TLEN   2048
#define EMB    384
#define TT     16            // frames per tile (MMA M)
#define NTILES (TLEN / TT)   // 128
#define NTH    256           // 8 warps
#define KMAX   64            // max compacted tokens per tile (worst case ~59)
#define KC     16            // tokens per MMA chunk
#define EPAD   388           // emb smem row stride (floats), bank-conflict-free

__device__ float4 g_tok[BATCH][NTOK];   // {center, 1/sig, reach (-1e30 if dropped), token_id bits}
__device__ float  g_cumend[BATCH];
__device__ int    g_wlo[BATCH][NTILES];
__device__ int    g_whi[BATCH][NTILES];

// ---------------- Kernel A: merge + scan + token params + per-tile windows ----------------
__global__ void prep_kernel(const int* __restrict__ text, const int* __restrict__ durs) {
    int b = blockIdx.x;
    int i = threadIdx.x;
    __shared__ float a[NTOK];

    if (i < NTILES) { g_wlo[b][i] = NTOK; g_whi[b][i] = 0; }

    float d = 0.0f; int tx = 0;
    if (i < NTOK) {
        if (i == 0) { d = (float)durs[b * LSEQ]; tx = text[b * LSEQ]; }
        else {
            d  = (float)(durs[b * LSEQ + 2 * i - 1] + durs[b * LSEQ + 2 * i]);
            tx = text[b * LSEQ + 2 * i - 1];
        }
        a[i] = d;
    }
    __syncthreads();
    for (int off = 1; off < NTOK; off <<= 1) {
        float v = 0.0f;
        if (i < NTOK) { v = a[i]; if (i >= off) v += a[i - off]; }
        __syncthreads();
        if (i < NTOK) a[i] = v;
        __syncthreads();
    }
    if (i < NTOK) {
        float cum  = a[i];
        float c    = cum - 0.5f * d;
        float sig  = 0.5f * d + 1e-6f;
        float invs = 1.0f / sig;
        bool  kept = (tx != 0) && (d > 0.0f);
        float r = kept ? (3.5f * d + 0.51f) : -1e30f;   // z-cut = 7
        g_tok[b][i] = make_float4(c, invs, r, __int_as_float(tx));
        if (kept) {
            int k0 = max(0, (int)ceilf((c - r - ((float)TT - 0.5f)) * (1.0f / TT)));
            int k1 = min(NTILES - 1, (int)floorf((c + r - 0.5f) * (1.0f / TT)));
            for (int k = k0; k <= k1; ++k) {
                atomicMin(&g_wlo[b][k], i);
                atomicMax(&g_whi[b][k], i + 1);
            }
        }
        if (i == NTOK - 1) g_cumend[b] = cum;
    }
}

__device__ __forceinline__ uint32_t f2tf32(float f) {
    uint32_t r;
    asm("cvt.rna.tf32.f32 %0, %1;" : "=r"(r) : "f"(f));
    return r;
}

// ---------------- Kernel B: tensor-core gaussian upsample ----------------
__global__ void __launch_bounds__(NTH, 4)
gauss_kernel(const float* __restrict__ emb, float* __restrict__ out) {
    const int b    = blockIdx.y;
    const int tile = blockIdx.x;
    const int t0   = tile * TT;
    const int tid  = threadIdx.x;
    const int wid  = tid >> 5;
    const int lane = tid & 31;
    const int g    = lane >> 2;        // group id 0..7
    const int tq   = lane & 3;         // thread-in-group 0..3
    const int n0   = wid * 48;         // this warp's output-column base

    __shared__ __align__(16) float s_e[KC][EPAD];   // emb chunk [k][n], padded stride
    __shared__ float w_s[KC][TT];                   // weights  [k][m]
    __shared__ float s_c[KMAX], s_is[KMAX], s_cf[KMAX];
    __shared__ int   s_tok[KMAX];
    __shared__ float wsum[TT], scale_s[TT];
    __shared__ int   s_cnt;

    if (tid < TT) wsum[tid] = 0.0f;
    if (tid == 0) s_cnt = 0;
    __syncthreads();

    // ---- compact per-token-reach-filtered token list for this tile ----
    const float tlo = (float)t0 + 0.5f;
    const float thi = (float)t0 + (float)TT - 0.5f;
    {
        const int nlo = g_wlo[b][tile];
        const int nhi = g_whi[b][tile];
        for (int n = nlo + tid; n < nhi; n += NTH) {
            float4 p = g_tok[b][n];
            if (p.x - p.z <= thi && p.x + p.z >= tlo) {
                int s = atomicAdd(&s_cnt, 1);
                if (s < KMAX) {
                    s_c[s]   = p.x;
                    s_is[s]  = p.y;
                    s_cf[s]  = 0.3989422804014327f * p.y;
                    s_tok[s] = __float_as_int(p.w);
                }
            }
        }
    }
    __syncthreads();
    const int cnt     = min(s_cnt, KMAX);
    const int cnt_pad = (cnt + KC - 1) & ~(KC - 1);
    // pad with harmless tokens: w = 0*exp(0) = 0, emb row 0 valid (no NaN)
    for (int s = cnt + tid; s < cnt_pad; s += NTH) {
        s_c[s] = 0.0f; s_is[s] = 0.0f; s_cf[s] = 0.0f; s_tok[s] = 0;
    }
    __syncthreads();

    // accumulators: 6 n8-tiles x 4 regs
    float acc[6][4];
#pragma unroll
    for (int j = 0; j < 6; ++j)
#pragma unroll
        for (int q = 0; q < 4; ++q) acc[j][q] = 0.0f;

    const float4* emb4 = reinterpret_cast<const float4*>(emb);

    for (int kc = 0; kc < cnt_pad; kc += KC) {
        // ---- phase 1: weights for this chunk; thread owns (k = tid>>4, m = tid&15) ----
        {
            const int   km = tid >> 4;          // 0..15
            const int   m  = tid & (TT - 1);
            const float tm = (float)(t0 + m) + 0.5f;
            const int   s  = kc + km;
            float z = (tm - s_c[s]) * s_is[s];
            float w = s_cf[s] * __expf(-0.5f * z * z);
            w_s[km][m] = w;
            if (w != 0.0f) atomicAdd(&wsum[m], w);
        }
        // ---- stage emb rows for this chunk: 16 rows x 96 float4 ----
        for (int i = tid; i < KC * (EMB / 4); i += NTH) {
            int r  = i / (EMB / 4);
            int c4 = i - r * (EMB / 4);
            float4 v = emb4[(size_t)s_tok[kc + r] * (EMB / 4) + c4];
            *reinterpret_cast<float4*>(&s_e[r][4 * c4]) = v;
        }
        __syncthreads();

        // ---- MMA: D[16, 48] += W[16, 16] x E[16, 48] per warp ----
#pragma unroll
        for (int kk = 0; kk < 2; ++kk) {
            const int kb = kk * 8;
            uint32_t a0 = f2tf32(w_s[kb + tq][g]);
            uint32_t a1 = f2tf32(w_s[kb + tq][g + 8]);
            uint32_t a2 = f2tf32(w_s[kb + tq + 4][g]);
            uint32_t a3 = f2tf32(w_s[kb + tq + 4][g + 8]);
#pragma unroll
            for (int j = 0; j < 6; ++j) {
                uint32_t b0 = f2tf32(s_e[kb + tq][n0 + 8 * j + g]);
                uint32_t b1 = f2tf32(s_e[kb + tq + 4][n0 + 8 * j + g]);
                asm volatile(
                    "mma.sync.aligned.m16n8k8.row.col.f32.tf32.tf32.f32 "
                    "{%0,%1,%2,%3}, {%4,%5,%6,%7}, {%8,%9}, {%0,%1,%2,%3};"
                    : "+f"(acc[j][0]), "+f"(acc[j][1]), "+f"(acc[j][2]), "+f"(acc[j][3])
                    : "r"(a0), "r"(a1), "r"(a2), "r"(a3), "r"(b0), "r"(b1));
            }
        }
        __syncthreads();
    }

    // ---- normalization scales ----
    if (tid < TT) {
        float tmv = (float)(t0 + tid) + 0.5f;
        scale_s[tid] = (tmv < g_cumend[b]) ? (1.0f / (wsum[tid] + 1e-6f)) : 0.0f;
    }
    __syncthreads();

    // ---- epilogue: scale + store. thread holds D rows g, g+8, cols n0+8j+2tq..+1 ----
    {
        const float sg  = scale_s[g];
        const float sg8 = scale_s[g + 8];
        float2* outp = reinterpret_cast<float2*>(out);
        const size_t rbase = (size_t)(b * TLEN + t0);
#pragma unroll
        for (int j = 0; j < 6; ++j) {
            int colh = (n0 + 8 * j + 2 * tq) >> 1;   // float2 index
            outp[(rbase + g)     * (EMB / 2) + colh] = make_float2(acc[j][0] * sg,  acc[j][1] * sg);
            outp[(rbase + g + 8) * (EMB / 2) + colh] = make_float2(acc[j][2] * sg8, acc[j][3] * sg8);
        }
    }
}

extern "C" void kernel_launch(void* const* d_in, const int* in_sizes, int n_in,
                              void* d_out, int out_size) {
    const int*   text = (const int*)d_in[0];
    const int*   durs = (const int*)d_in[1];
    const float* emb  = (const float*)d_in[2];
    float* out = (float*)d_out;

    prep_kernel<<<BATCH, 544>>>(text, durs);
    dim3 grid(NTILES, BATCH);
    gauss_kernel<<<grid, NTH>>>(emb, out);
}

// round 6
// speedup vs baseline: 1.3103x; 1.3103x over previous
#include <cuda_runtime.h>
#include <cuda_bf16.h>

#define BATCH  32
#define LSEQ   1025
#define NTOK   513
#define TLEN   2048
#define EMB    384
#define TT     16            // frames per tile
#define NTILES (TLEN / TT)   // 128
#define NTH    192           // threads per block; each owns 2 embedding cols
#define CHMAX  64            // max compacted tokens per tile

__device__ float4 g_tok[BATCH][NTOK];   // {center, 1/sig, reach (-1e30 if dropped), token_id bits}
__device__ float  g_cumend[BATCH];
__device__ int    g_wlo[BATCH][NTILES];
__device__ int    g_whi[BATCH][NTILES];

// ---------------- Kernel A: merge + scan + token params + per-tile windows ----------------
__global__ void prep_kernel(const int* __restrict__ text, const int* __restrict__ durs) {
    int b = blockIdx.x;
    int i = threadIdx.x;
    __shared__ float a[NTOK];

    if (i < NTILES) { g_wlo[b][i] = NTOK; g_whi[b][i] = 0; }

    float d = 0.0f; int tx = 0;
    if (i < NTOK) {
        if (i == 0) { d = (float)durs[b * LSEQ]; tx = text[b * LSEQ]; }
        else {
            d  = (float)(durs[b * LSEQ + 2 * i - 1] + durs[b * LSEQ + 2 * i]);
            tx = text[b * LSEQ + 2 * i - 1];
        }
        a[i] = d;
    }
    __syncthreads();
    // Hillis-Steele inclusive scan
    for (int off = 1; off < NTOK; off <<= 1) {
        float v = 0.0f;
        if (i < NTOK) { v = a[i]; if (i >= off) v += a[i - off]; }
        __syncthreads();
        if (i < NTOK) a[i] = v;
        __syncthreads();
    }
    if (i < NTOK) {
        float cum  = a[i];
        float c    = cum - 0.5f * d;
        float sig  = 0.5f * d + 1e-6f;
        float invs = 1.0f / sig;
        bool  kept = (tx != 0) && (d > 0.0f);
        // z-cut = 5.5: dropped weights <= 2e-7 vs wsum >= 0.08 -> rel pert <= ~5e-5
        float r = kept ? (2.75f * d + 0.51f) : -1e30f;
        g_tok[b][i] = make_float4(c, invs, r, __int_as_float(tx));
        if (kept) {
            int k0 = max(0, (int)ceilf((c - r - ((float)TT - 0.5f)) * (1.0f / TT)));
            int k1 = min(NTILES - 1, (int)floorf((c + r - 0.5f) * (1.0f / TT)));
            for (int k = k0; k <= k1; ++k) {
                atomicMin(&g_wlo[b][k], i);
                atomicMax(&g_whi[b][k], i + 1);
            }
        }
        if (i == NTOK - 1) g_cumend[b] = cum;
    }
}

// ---------------- Kernel B: windowed gaussian upsample ----------------
__global__ void __launch_bounds__(NTH, 4)
gauss_kernel(const float* __restrict__ emb, float* __restrict__ out) {
    const int b    = blockIdx.y;
    const int tile = blockIdx.x;
    const int t0   = tile * TT;
    const int tid  = threadIdx.x;       // owns embedding cols 2*tid, 2*tid+1

    __shared__ __align__(16) float w_s[CHMAX][TT];
    __shared__ float s_c[CHMAX], s_is[CHMAX], s_cf[CHMAX];
    __shared__ int   s_tok[CHMAX];
    __shared__ float wsum[TT], scale_s[TT];
    __shared__ int   s_cnt;

    if (tid < TT) wsum[tid] = 0.0f;
    if (tid == 0) s_cnt = 0;
    __syncthreads();

    // ---- compact per-token-reach-filtered token list for this tile ----
    const float tlo = (float)t0 + 0.5f;
    const float thi = (float)t0 + (float)TT - 0.5f;
    {
        const int nlo = g_wlo[b][tile];
        const int nhi = g_whi[b][tile];
        for (int n = nlo + tid; n < nhi; n += NTH) {
            float4 p = g_tok[b][n];
            if (p.x - p.z <= thi && p.x + p.z >= tlo) {
                int s = atomicAdd(&s_cnt, 1);
                if (s < CHMAX) {
                    s_c[s]   = p.x;
                    s_is[s]  = p.y;
                    s_cf[s]  = 0.3989422804014327f * p.y;
                    s_tok[s] = __float_as_int(p.w);
                }
            }
        }
    }
    __syncthreads();
    const int cnt = min(s_cnt, CHMAX);

    // ---- phase 1: weights -> smem; per-thread register wsum (frame fixed = tid & 15) ----
    {
        const int   myt = tid & (TT - 1);
        const float tm  = (float)(t0 + myt) + 0.5f;
        float wl = 0.0f;
        for (int idx = tid; idx < cnt * TT; idx += NTH) {
            int nl = idx >> 4;
            float z = (tm - s_c[nl]) * s_is[nl];
            float w = s_cf[nl] * __expf(-0.5f * z * z);
            w_s[nl][myt] = w;
            wl += w;
        }
        atomicAdd(&wsum[myt], wl);
    }
    __syncthreads();

    if (tid < TT) {
        float tmv = (float)(t0 + tid) + 0.5f;
        scale_s[tid] = (tmv < g_cumend[b]) ? (1.0f / (wsum[tid] + 1e-6f)) : 0.0f;
    }

    // ---- phase 2: acc[t] += w[t] * emb[tok][2tid..2tid+1], 4-token unroll, MLP=4 ----
    float2 acc[TT];
#pragma unroll
    for (int t = 0; t < TT; ++t) acc[t] = make_float2(0.0f, 0.0f);

    const float2* embp = reinterpret_cast<const float2*>(emb);

    int cs = 0;
    for (; cs + 4 <= cnt; cs += 4) {
        float2 e0 = embp[s_tok[cs + 0] * (EMB / 2) + tid];
        float2 e1 = embp[s_tok[cs + 1] * (EMB / 2) + tid];
        float2 e2 = embp[s_tok[cs + 2] * (EMB / 2) + tid];
        float2 e3 = embp[s_tok[cs + 3] * (EMB / 2) + tid];
#pragma unroll
        for (int u = 0; u < 4; ++u) {
            float2 ev = (u == 0) ? e0 : (u == 1) ? e1 : (u == 2) ? e2 : e3;
            const float4* wp = reinterpret_cast<const float4*>(w_s[cs + u]);
#pragma unroll
            for (int j = 0; j < TT / 4; ++j) {
                float4 w4 = wp[j];
                acc[4 * j + 0].x += w4.x * ev.x;  acc[4 * j + 0].y += w4.x * ev.y;
                acc[4 * j + 1].x += w4.y * ev.x;  acc[4 * j + 1].y += w4.y * ev.y;
                acc[4 * j + 2].x += w4.z * ev.x;  acc[4 * j + 2].y += w4.z * ev.y;
                acc[4 * j + 3].x += w4.w * ev.x;  acc[4 * j + 3].y += w4.w * ev.y;
            }
        }
    }
    for (; cs < cnt; ++cs) {
        float2 ev = embp[s_tok[cs] * (EMB / 2) + tid];
        const float4* wp = reinterpret_cast<const float4*>(w_s[cs]);
#pragma unroll
        for (int j = 0; j < TT / 4; ++j) {
            float4 w4 = wp[j];
            acc[4 * j + 0].x += w4.x * ev.x;  acc[4 * j + 0].y += w4.x * ev.y;
            acc[4 * j + 1].x += w4.y * ev.x;  acc[4 * j + 1].y += w4.y * ev.y;
            acc[4 * j + 2].x += w4.z * ev.x;  acc[4 * j + 2].y += w4.z * ev.y;
            acc[4 * j + 3].x += w4.w * ev.x;  acc[4 * j + 3].y += w4.w * ev.y;
        }
    }
    __syncthreads();   // scale_s ready

    // ---- normalize + store (float2, coalesced per frame) ----
    float2* outp = reinterpret_cast<float2*>(out);
    size_t base = ((size_t)(b * TLEN + t0)) * (EMB / 2) + tid;
#pragma unroll
    for (int tt = 0; tt < TT; ++tt) {
        float s = scale_s[tt];
        outp[base + (size_t)tt * (EMB / 2)] = make_float2(acc[tt].x * s, acc[tt].y * s);
    }
}

extern "C" void kernel_launch(void* const* d_in, const int* in_sizes, int n_in,
                              void* d_out, int out_size) {
    const int*   text = (const int*)d_in[0];
    const int*   durs = (const int*)d_in[1];
    const float* emb  = (const float*)d_in[2];
    float* out = (float*)d_out;

    prep_kernel<<<BATCH, 544>>>(text, durs);
    dim3 grid(NTILES, BATCH);
    gauss_kernel<<<grid, NTH>>>(emb, out);
}